// round 1
// baseline (speedup 1.0000x reference)
#include <cuda_runtime.h>
#include <cuda_bf16.h>

// Problem constants (dataset is fixed: N=200000, E=12800000, lamb=0.5)
#define MAXN 200000
#define MAXBITS ((MAXN + 31) / 32)
#define HIST_BITS 21
#define HIST_SIZE (1 << HIST_BITS)   // keys: (x<<20)|(s1<<10)|s0, s0,s1 < 1024

// Scratch (device globals: no runtime allocation allowed)
__device__ int          g_cnt[MAXN];        // packed: low16 = s0 (state-1 nbrs), high16 = s1
__device__ unsigned int g_xbits[MAXBITS];   // bitmask of x[i] > 0
__device__ int          g_hist[HIST_SIZE];  // key histogram
__device__ float        g_sums[2];          // [0]=sum w, [1]=sum w*nll

// ---------------------------------------------------------------------------
// K0: zero scratch (hist + cnt + sums). xbits is fully overwritten by K1.
__global__ void zero_all(int n) {
    int i = blockIdx.x * blockDim.x + threadIdx.x;
    int stride = gridDim.x * blockDim.x;
    for (int j = i; j < HIST_SIZE; j += stride) g_hist[j] = 0;
    for (int j = i; j < n; j += stride) g_cnt[j] = 0;
    if (i < 2) g_sums[i] = 0.0f;
}

// ---------------------------------------------------------------------------
// K1: build 25KB bitmask of x (L1-resident during the edge kernel)
__global__ void build_bits(const int* __restrict__ x, int n) {
    int w = blockIdx.x * blockDim.x + threadIdx.x;
    int base = w * 32;
    if (base >= n) return;
    unsigned int m = 0;
    int lim = min(32, n - base);
    for (int k = 0; k < lim; k++) {
        if (x[base + k] > 0) m |= (1u << k);
    }
    g_xbits[w] = m;
}

// ---------------------------------------------------------------------------
// K2: edge scatter. One REDG atomic per edge into the packed counter.
__device__ __forceinline__ void process_edge(int r, int c) {
    unsigned int bit = (g_xbits[((unsigned)c) >> 5] >> (c & 31)) & 1u;
    // is_one -> s0 += 1 (low half); else s1 += 1 (high half)
    atomicAdd(&g_cnt[r], bit ? 1 : 0x10000);
}

__global__ void edge_kernel(const int* __restrict__ row,
                            const int* __restrict__ col,
                            int e4, int tail) {
    int t = blockIdx.x * blockDim.x + threadIdx.x;
    if (t < e4) {
        int4 r = ((const int4*)row)[t];
        int4 c = ((const int4*)col)[t];
        process_edge(r.x, c.x);
        process_edge(r.y, c.y);
        process_edge(r.z, c.z);
        process_edge(r.w, c.w);
    }
    if (t < tail) {
        int e = e4 * 4 + t;
        process_edge(row[e], col[e]);
    }
}

// ---------------------------------------------------------------------------
// K3: key histogram over (x, s0, s1)
__device__ __forceinline__ int node_key(int cnt, int xv) {
    int s0 = cnt & 0xFFFF;
    int s1 = (cnt >> 16) & 0xFFFF;
    s0 = min(s0, 1023);
    s1 = min(s1, 1023);
    return (xv << 20) | (s1 << 10) | s0;
}

__global__ void hist_kernel(const int* __restrict__ x, int n) {
    int i = blockIdx.x * blockDim.x + threadIdx.x;
    if (i >= n) return;
    atomicAdd(&g_hist[node_key(g_cnt[i], x[i] > 0 ? 1 : 0)], 1);
}

// ---------------------------------------------------------------------------
// K4: per-node weight + NLL, block-reduced, atomics into g_sums
__global__ void accum_kernel(const float* __restrict__ out2,
                             const int* __restrict__ x,
                             const int* __restrict__ y, int n) {
    int i = blockIdx.x * blockDim.x + threadIdx.x;
    float w = 0.0f, wn = 0.0f;
    if (i < n) {
        int c = g_hist[node_key(g_cnt[i], x[i] > 0 ? 1 : 0)];
        w = rsqrtf((float)c);                         // count^(-0.5)
        float o0 = out2[2 * i];
        float o1 = out2[2 * i + 1];
        float m = fmaxf(o0, o1);
        float other = fminf(o0, o1);
        float lse = m + log1pf(expf(other - m));      // stable 2-class logsumexp
        float sel = (y[i] == 0) ? o0 : o1;
        wn = w * (lse - sel);                         // w * nll
    }
    __shared__ float sw[256];
    __shared__ float swn[256];
    int tid = threadIdx.x;
    sw[tid] = w;
    swn[tid] = wn;
    __syncthreads();
    for (int s = 128; s > 0; s >>= 1) {
        if (tid < s) {
            sw[tid] += sw[tid + s];
            swn[tid] += swn[tid + s];
        }
        __syncthreads();
    }
    if (tid == 0) {
        atomicAdd(&g_sums[0], sw[0]);
        atomicAdd(&g_sums[1], swn[0]);
    }
}

// ---------------------------------------------------------------------------
// K5: scalar finalize
__global__ void final_kernel(float* out) {
    out[0] = g_sums[1] / g_sums[0];
}

// ---------------------------------------------------------------------------
extern "C" void kernel_launch(void* const* d_in, const int* in_sizes, int n_in,
                              void* d_out, int out_size) {
    const float* out2 = (const float*)d_in[0];   // (N,2) float32
    const int* x = (const int*)d_in[1];          // (N,) int32
    const int* y = (const int*)d_in[2];          // (N,) int32
    const int* eidx = (const int*)d_in[3];       // (2,E) int32

    int N = in_sizes[1];
    if (N > MAXN) N = MAXN;                      // dataset is fixed at 200000
    int E = in_sizes[3] / 2;
    const int* row = eidx;
    const int* col = eidx + E;

    const int T = 256;

    // K0: zero scratch
    zero_all<<<2048, T>>>(N);

    // K1: x bitmask
    int nwords = (N + 31) / 32;
    build_bits<<<(nwords + T - 1) / T, T>>>(x, N);

    // K2: edge scatter
    int e4 = E / 4;
    int tail = E - e4 * 4;
    int nthreads = e4 > tail ? e4 : tail;
    edge_kernel<<<(nthreads + T - 1) / T, T>>>(row, col, e4, tail);

    // K3: key histogram
    hist_kernel<<<(N + T - 1) / T, T>>>(x, N);

    // K4: weighted NLL reduction
    accum_kernel<<<(N + T - 1) / T, T>>>(out2, x, y, N);

    // K5: finalize scalar
    final_kernel<<<1, 1>>>((float*)d_out);
}